// round 8
// baseline (speedup 1.0000x reference)
#include <cuda_runtime.h>
#include <cstdint>

#define NN 100000
#define EE 600000
#define PP 100000
#define D  128

__device__ float g_hA[(size_t)NN * D];
__device__ float g_hB[(size_t)NN * D];
__device__ float g_agg[(size_t)NN * D];
__device__ float g_cnt[NN];

// packed f32x2 helpers
__device__ __forceinline__ void fma2(unsigned long long& acc,
                                     unsigned long long a, unsigned long long b) {
    asm("fma.rn.f32x2 %0, %1, %2, %0;" : "+l"(acc) : "l"(a), "l"(b));
}
__device__ __forceinline__ unsigned long long bcast2(float v) {
    unsigned long long r;
    asm("mov.b64 %0, {%1, %1};" : "=l"(r) : "f"(v));
    return r;
}
__device__ __forceinline__ void unpack2(unsigned long long p, float& lo, float& hi) {
    asm("mov.b64 {%0, %1}, %2;" : "=f"(lo), "=f"(hi) : "l"(p));
}
__device__ __forceinline__ void lds_v2u64(unsigned long long& a, unsigned long long& b,
                                          const void* p) {
    asm volatile("{ .reg .u64 t; cvta.to.shared.u64 t, %2; "
                 "ld.shared.v2.u64 {%0, %1}, [t]; }"
                 : "=l"(a), "=l"(b) : "l"(p));
}

// ---------------------------------------------------------------------------
// Edge scatter: agg[dst] += w * h[src], cnt[dst] += 1
// ---------------------------------------------------------------------------
__global__ void __launch_bounds__(256) edge_kernel(
    const int* __restrict__ src, const int* __restrict__ dst,
    const float* __restrict__ w, const float* __restrict__ h)
{
    int t = blockIdx.x * blockDim.x + threadIdx.x;
    int e = t >> 5;
    if (e >= EE) return;
    int lane = t & 31;
    int s = __ldg(src + e);
    int d = __ldg(dst + e);
    float we = __ldg(w + e);
    float4 v = __ldg((const float4*)(h + (size_t)s * D) + lane);
    v.x *= we; v.y *= we; v.z *= we; v.w *= we;
    float* a = g_agg + (size_t)d * D + lane * 4;
    asm volatile("red.global.add.v4.f32 [%0], {%1,%2,%3,%4};"
                 :: "l"(a), "f"(v.x), "f"(v.y), "f"(v.z), "f"(v.w) : "memory");
    if (lane == 0) atomicAdd(g_cnt + d, 1.0f);
}

// ---------------------------------------------------------------------------
// Fused SAGE node update: out = [h | agg/max(cnt,1)] @ [Wself;Wneigh] + b
// 128x128 tile, BK=16, 256 threads, 8x8 micro-tile, transposed-A smem,
// register prefetch, packed fma.rn.f32x2 inner loop (pairs over M).
// ---------------------------------------------------------------------------
#define BMN 128
#define BKN 16
#define APAD 132

__global__ void __launch_bounds__(256, 2) sage_node_kernel(
    const float* __restrict__ h_in,
    const float* __restrict__ Wself, const float* __restrict__ Wneigh,
    const float* __restrict__ bias,
    float* __restrict__ h_out, int do_relu)
{
    __shared__ float As[BKN][APAD];   // [k][m] transposed
    __shared__ float Bs[BKN][128];    // [k][n]
    __shared__ float rcp_s[BMN];

    int t = threadIdx.x;
    int row_blk = blockIdx.x * BMN;

    if (t < BMN) {
        int g = row_blk + t;
        float c = (g < NN) ? g_cnt[g] : 1.0f;
        rcp_s[t] = 1.0f / fmaxf(c, 1.0f);
    }

    int tm = t >> 4;        // 0..15
    int tn = t & 15;        // 0..15
    int r0 = tm * 8;
    int c0 = tn * 4;

    // acc2[c][rp]: c = 8 output cols (c0..c0+3, 64+c0..64+c0+3),
    // rp = 4 row-pairs (rows r0+2rp, r0+2rp+1) packed in f32x2
    unsigned long long acc2[8][4];
    #pragma unroll
    for (int c = 0; c < 8; c++)
        #pragma unroll
        for (int rp = 0; rp < 4; rp++) acc2[c][rp] = 0ULL;

    float4 pa[2], pb[2];
    int arow[2];

    auto load_tile = [&](int kb, float4* ra, float4* rb, int* rrow) {
        const float* Abase = (kb < 8) ? h_in : g_agg;
        int koff = (kb < 8) ? kb * BKN : kb * BKN - 128;
        #pragma unroll
        for (int i = 0; i < 2; i++) {
            int idx = t + i * 256;
            int ar = idx >> 2;
            int aq = idx & 3;
            rrow[i] = ar;
            int g = row_blk + ar;
            float4 v = make_float4(0.f, 0.f, 0.f, 0.f);
            if (g < NN)
                v = __ldg((const float4*)(Abase + (size_t)g * D + koff) + aq);
            ra[i] = v;
        }
        #pragma unroll
        for (int i = 0; i < 2; i++) {
            int idx = t + i * 256;
            int kk = idx >> 5;
            int j4 = idx & 31;
            int kg = kb * BKN + kk;
            const float* W = (kg < 128) ? Wself : Wneigh;
            rb[i] = __ldg((const float4*)(W + (size_t)(kg & 127) * D) + j4);
        }
    };

    load_tile(0, pa, pb, arow);
    __syncthreads();   // rcp_s ready

    #pragma unroll 1
    for (int kb = 0; kb < 16; kb++) {
        bool is_agg = (kb >= 8);
        #pragma unroll
        for (int i = 0; i < 2; i++) {
            int idx = t + i * 256;
            int aq = idx & 3;
            float sc = is_agg ? rcp_s[arow[i]] : 1.0f;
            As[aq * 4 + 0][arow[i]] = pa[i].x * sc;
            As[aq * 4 + 1][arow[i]] = pa[i].y * sc;
            As[aq * 4 + 2][arow[i]] = pa[i].z * sc;
            As[aq * 4 + 3][arow[i]] = pa[i].w * sc;
        }
        #pragma unroll
        for (int i = 0; i < 2; i++) {
            int idx = t + i * 256;
            int kk = idx >> 5;
            int j4 = idx & 31;
            *(float4*)&Bs[kk][j4 * 4] = pb[i];
        }
        __syncthreads();

        if (kb + 1 < 16) load_tile(kb + 1, pa, pb, arow);

        #pragma unroll
        for (int k = 0; k < BKN; k++) {
            unsigned long long a2[4];
            lds_v2u64(a2[0], a2[1], &As[k][r0]);
            lds_v2u64(a2[2], a2[3], &As[k][r0 + 4]);
            float4 b0 = *(float4*)&Bs[k][c0];
            float4 b1 = *(float4*)&Bs[k][64 + c0];
            unsigned long long b2[8];
            b2[0] = bcast2(b0.x); b2[1] = bcast2(b0.y);
            b2[2] = bcast2(b0.z); b2[3] = bcast2(b0.w);
            b2[4] = bcast2(b1.x); b2[5] = bcast2(b1.y);
            b2[6] = bcast2(b1.z); b2[7] = bcast2(b1.w);
            #pragma unroll
            for (int c = 0; c < 8; c++)
                #pragma unroll
                for (int rp = 0; rp < 4; rp++)
                    fma2(acc2[c][rp], a2[rp], b2[c]);
        }
        __syncthreads();
    }

    float4 bb0 = __ldg((const float4*)(bias + c0));
    float4 bb1 = __ldg((const float4*)(bias + 64 + c0));
    float bA[8] = {bb0.x, bb0.y, bb0.z, bb0.w, bb1.x, bb1.y, bb1.z, bb1.w};

    #pragma unroll
    for (int rp = 0; rp < 4; rp++) {
        float vlo[8], vhi[8];
        #pragma unroll
        for (int c = 0; c < 8; c++) {
            unpack2(acc2[c][rp], vlo[c], vhi[c]);
            vlo[c] += bA[c]; vhi[c] += bA[c];
            if (do_relu) { vlo[c] = fmaxf(vlo[c], 0.f); vhi[c] = fmaxf(vhi[c], 0.f); }
        }
        int glo = row_blk + r0 + 2 * rp;
        int ghi = glo + 1;
        if (glo < NN) {
            *(float4*)(h_out + (size_t)glo * D + c0) = make_float4(vlo[0], vlo[1], vlo[2], vlo[3]);
            *(float4*)(h_out + (size_t)glo * D + 64 + c0) = make_float4(vlo[4], vlo[5], vlo[6], vlo[7]);
        }
        if (ghi < NN) {
            *(float4*)(h_out + (size_t)ghi * D + c0) = make_float4(vhi[0], vhi[1], vhi[2], vhi[3]);
            *(float4*)(h_out + (size_t)ghi * D + 64 + c0) = make_float4(vhi[4], vhi[5], vhi[6], vhi[7]);
        }
    }
}

// ---------------------------------------------------------------------------
// Fused link predictor, one launch for pos+neg, f32x2 inner loops.
// ---------------------------------------------------------------------------
#define PB 782
#define ZT_PAD 132
#define PRED_BK 32
#define SMEM_PRED ((128 * ZT_PAD + PRED_BK * 128) * 4)

__global__ void __launch_bounds__(256, 2) pred_kernel(
    const float* __restrict__ h,
    const int* __restrict__ pos_a, const int* __restrict__ pos_b,
    const int* __restrict__ neg_a, const int* __restrict__ neg_b,
    const float* __restrict__ pw1, const float* __restrict__ pb1,
    const float* __restrict__ pw2, const float* __restrict__ pb2,
    const float* __restrict__ pw3, const float* __restrict__ pb3,
    float* __restrict__ out)
{
    extern __shared__ float sm[];
    float (*Zt)[ZT_PAD] = (float(*)[ZT_PAD])sm;
    float (*Bs)[128]    = (float(*)[128])(sm + 128 * ZT_PAD);

    int t = threadIdx.x;
    bool is_neg = blockIdx.x >= PB;
    int p0 = (is_neg ? (blockIdx.x - PB) : blockIdx.x) * 128;
    const int* ia = is_neg ? neg_a : pos_a;
    const int* ib = is_neg ? neg_b : pos_b;
    float* outp = out + (is_neg ? PP : 0);

    // --- stage 0: Zt[:, pair] = h[ia]*h[ib] ---
    {
        int zrow = t >> 1;
        int half = t & 1;
        int gp = p0 + zrow;
        bool valid = gp < PP;
        int sa = valid ? __ldg(ia + gp) : 0;
        int sb = valid ? __ldg(ib + gp) : 0;
        const float4* ha = (const float4*)(h + (size_t)sa * D) + half * 16;
        const float4* hb = (const float4*)(h + (size_t)sb * D) + half * 16;
        #pragma unroll
        for (int i = 0; i < 16; i++) {
            float4 va = __ldg(ha + i);
            float4 vb = __ldg(hb + i);
            int f = half * 64 + i * 4;
            Zt[f + 0][zrow] = va.x * vb.x;
            Zt[f + 1][zrow] = va.y * vb.y;
            Zt[f + 2][zrow] = va.z * vb.z;
            Zt[f + 3][zrow] = va.w * vb.w;
        }
    }

    int tm = t >> 4, tn = t & 15;
    int r0 = tm * 8, c0 = tn * 4;

    #pragma unroll 1
    for (int stage = 0; stage < 2; stage++) {
        const float* W = stage ? pw2 : pw1;
        const float* B = stage ? pb2 : pb1;

        unsigned long long acc2[8][4];
        #pragma unroll
        for (int c = 0; c < 8; c++)
            #pragma unroll
            for (int rp = 0; rp < 4; rp++) acc2[c][rp] = 0ULL;

        #pragma unroll 1
        for (int kb = 0; kb < 128; kb += PRED_BK) {
            __syncthreads();
            #pragma unroll
            for (int i = 0; i < 4; i++) {
                int idx = t + i * 256;
                int kk = idx >> 5;
                int j4 = idx & 31;
                *(float4*)&Bs[kk][j4 * 4] =
                    __ldg((const float4*)(W + (size_t)(kb + kk) * D) + j4);
            }
            __syncthreads();

            #pragma unroll
            for (int k = 0; k < PRED_BK; k++) {
                unsigned long long a2[4];
                lds_v2u64(a2[0], a2[1], &Zt[kb + k][r0]);
                lds_v2u64(a2[2], a2[3], &Zt[kb + k][r0 + 4]);
                float4 b0 = *(float4*)&Bs[k][c0];
                float4 b1 = *(float4*)&Bs[k][64 + c0];
                unsigned long long b2[8];
                b2[0] = bcast2(b0.x); b2[1] = bcast2(b0.y);
                b2[2] = bcast2(b0.z); b2[3] = bcast2(b0.w);
                b2[4] = bcast2(b1.x); b2[5] = bcast2(b1.y);
                b2[6] = bcast2(b1.z); b2[7] = bcast2(b1.w);
                #pragma unroll
                for (int c = 0; c < 8; c++)
                    #pragma unroll
                    for (int rp = 0; rp < 4; rp++)
                        fma2(acc2[c][rp], a2[rp], b2[c]);
            }
        }

        float4 bb0 = __ldg((const float4*)(B + c0));
        float4 bb1 = __ldg((const float4*)(B + 64 + c0));
        float bA[8] = {bb0.x, bb0.y, bb0.z, bb0.w, bb1.x, bb1.y, bb1.z, bb1.w};
        __syncthreads();   // everyone done reading Zt
        #pragma unroll
        for (int rp = 0; rp < 4; rp++) {
            #pragma unroll
            for (int c = 0; c < 8; c++) {
                float lo, hi;
                unpack2(acc2[c][rp], lo, hi);
                lo = fmaxf(lo + bA[c], 0.f);
                hi = fmaxf(hi + bA[c], 0.f);
                int col = (c < 4) ? (c0 + c) : (64 + c0 + c - 4);
                Zt[col][r0 + 2 * rp] = lo;
                Zt[col][r0 + 2 * rp + 1] = hi;
            }
        }
        __syncthreads();
    }

    // --- final: out = Zt^T @ pw3 + pb3 ---
    {
        int rr = t >> 1;
        int part = t & 1;
        float s = 0.f;
        #pragma unroll
        for (int j = 0; j < 64; j++) {
            int k = part * 64 + j;
            s += Zt[k][rr] * __ldg(pw3 + k);
        }
        s += __shfl_xor_sync(0xffffffffu, s, 1);
        if (part == 0 && p0 + rr < PP)
            outp[p0 + rr] = s + __ldg(pb3);
    }
}

// ---------------------------------------------------------------------------
extern "C" void kernel_launch(void* const* d_in, const int* in_sizes, int n_in,
                              void* d_out, int out_size)
{
    const float* x     = (const float*)d_in[0];
    const int* src[3]  = {(const int*)d_in[1], (const int*)d_in[4], (const int*)d_in[7]};
    const int* dst[3]  = {(const int*)d_in[2], (const int*)d_in[5], (const int*)d_in[8]};
    const float* w[3]  = {(const float*)d_in[3], (const float*)d_in[6], (const float*)d_in[9]};
    const int* pos_src = (const int*)d_in[10];
    const int* pos_dst = (const int*)d_in[11];
    const int* neg_src = (const int*)d_in[12];
    const int* neg_dst = (const int*)d_in[13];
    const float* Wself[3]  = {(const float*)d_in[14], (const float*)d_in[17], (const float*)d_in[20]};
    const float* Wneigh[3] = {(const float*)d_in[15], (const float*)d_in[18], (const float*)d_in[21]};
    const float* bvec[3]   = {(const float*)d_in[16], (const float*)d_in[19], (const float*)d_in[22]};
    const float* pw1 = (const float*)d_in[23];
    const float* pb1 = (const float*)d_in[24];
    const float* pw2 = (const float*)d_in[25];
    const float* pb2 = (const float*)d_in[26];
    const float* pw3 = (const float*)d_in[27];
    const float* pb3 = (const float*)d_in[28];

    float* out = (float*)d_out;
    float* h_final = out + 2 * PP;

    void *agg_p, *cnt_p, *hA_p, *hB_p;
    cudaGetSymbolAddress(&agg_p, g_agg);
    cudaGetSymbolAddress(&cnt_p, g_cnt);
    cudaGetSymbolAddress(&hA_p, g_hA);
    cudaGetSymbolAddress(&hB_p, g_hB);
    float* hA = (float*)hA_p;
    float* hB = (float*)hB_p;

    static bool attr_set = false;
    if (!attr_set) {
        cudaFuncSetAttribute(pred_kernel, cudaFuncAttributeMaxDynamicSharedMemorySize, SMEM_PRED);
        attr_set = true;
    }

    const int edge_blocks = (EE * 32 + 255) / 256;
    const int node_blocks = (NN + BMN - 1) / BMN;

    const float* layer_in[3]  = {x, hA, hB};
    float*       layer_out[3] = {hA, hB, h_final};

    for (int l = 0; l < 3; l++) {
        cudaMemsetAsync(agg_p, 0, (size_t)NN * D * sizeof(float));
        cudaMemsetAsync(cnt_p, 0, (size_t)NN * sizeof(float));
        edge_kernel<<<edge_blocks, 256>>>(src[l], dst[l], w[l], layer_in[l]);
        sage_node_kernel<<<node_blocks, 256>>>(layer_in[l], Wself[l], Wneigh[l],
                                               bvec[l], layer_out[l], l < 2 ? 1 : 0);
    }

    pred_kernel<<<2 * PB, 256, SMEM_PRED>>>(h_final, pos_src, pos_dst,
        neg_src, neg_dst, pw1, pb1, pw2, pb2, pw3, pb3, out);
}